// round 6
// baseline (speedup 1.0000x reference)
#include <cuda_runtime.h>
#include <cstdint>
#include <cstddef>

// Problem constants
#define NN 512          // nodes
#define HD 1024         // hidden dim
#define NE 16384        // edges
#define KR 144          // padded Hmat rows (128 S + 4 bias2 + 12 zero pad)
#define ZS 16           // split-K factor for gemmS

// ---------------- scratch (device globals; no allocation allowed) ----------
__device__ __align__(16) float g_Spart[ZS * 128 * HD];   // split-K partials for S
__device__ __align__(16) float g_b2part[32 * 4 * HD];    // bias2 partials
__device__ __align__(16) float g_Hmat[KR * HD];          // 0..127 S, 128..131 bias2, 132..143 stay 0
__device__ __align__(16) float g_attC[NN * KR];          // folded attention (512 x 144)
__device__ __align__(16) float g_hp[NN * HD];            // h_prime (512 x 1024)
__device__ int      g_last[NN * NN];
__device__ float    g_SS1[132];
__device__ float    g_SS2[132];
__device__ float    g_outpart[(NN + 1) * 16];            // matvec partials
__device__ unsigned g_amax;

// ---------------- scatter: last-edge-wins per dense cell --------------------
__global__ void k_scatter(const int* __restrict__ er, const int* __restrict__ ec) {
    int k = blockIdx.x * blockDim.x + threadIdx.x;
    if (k < NE) atomicMax(&g_last[er[k] * NN + ec[k]], k);
}

// ---------------- amax of dense adj2 (cells with last-edge set; all >= 0) ---
__global__ void k_amax(const float* __restrict__ adj_vals) {
    __shared__ float sa[16];
    int idx = blockIdx.x * blockDim.x + threadIdx.x;
    int t = threadIdx.x, w = t >> 5, l = t & 31;
    float m = 0.f;
    int le = g_last[idx];
    if (le >= 0) m = 2.f * adj_vals[le];
    for (int o = 16; o > 0; o >>= 1) m = fmaxf(m, __shfl_xor_sync(0xffffffffu, m, o));
    if (l == 0) sa[w] = m;
    __syncthreads();
    if (t == 0) {
        float mm = 0.f;
        for (int i = 0; i < 16; i++) mm = fmaxf(mm, sa[i]);
        atomicMax(&g_amax, __float_as_uint(mm));
    }
}

// ---------------- bias2 partials: chunk rc of rho, 4 batch outputs ----------
__global__ void k_bias2(const float* __restrict__ W, const float* __restrict__ img) {
    int j  = blockIdx.x * 128 + threadIdx.x;
    int rc = blockIdx.y;
    int r0 = rc * 128;
    float a0 = 0.f, a1 = 0.f, a2 = 0.f, a3 = 0.f;
    #pragma unroll 4
    for (int rr = 0; rr < 128; rr++) {
        int rho = r0 + rr;
        float w = W[(size_t)rho * HD + j];
        int d = rho & 1023;
        a0 += img[d]        * w;
        a1 += img[1024 + d] * w;
        a2 += img[2048 + d] * w;
        a3 += img[3072 + d] * w;
    }
    g_b2part[(rc * 4 + 0) * HD + j] = a0;
    g_b2part[(rc * 4 + 1) * HD + j] = a1;
    g_b2part[(rc * 4 + 2) * HD + j] = a2;
    g_b2part[(rc * 4 + 3) * HD + j] = a3;
}

// ================= gemmS via packed f32x2 FMA (FFMA2) =======================
// Grid (8, 16): blockIdx.x = N-tile (128 cols), blockIdx.y = K-split (256 K).
// Tile M=128 x N=128, 256 threads, 8x8 micro with i-paired f32x2 accumulators.
__device__ __forceinline__ unsigned long long pack_dup(float x) {
    unsigned long long r;
    uint32_t u = __float_as_uint(x);
    asm("mov.b64 %0, {%1, %2};" : "=l"(r) : "r"(u), "r"(u));
    return r;
}
__device__ __forceinline__ void ffma2(unsigned long long& acc, unsigned long long a, unsigned long long b) {
    asm("fma.rn.f32x2 %0, %1, %2, %0;" : "+l"(acc) : "l"(a), "l"(b));
}
__device__ __forceinline__ void unpack2(unsigned long long v, float& lo, float& hi) {
    uint32_t a, b;
    asm("mov.b64 {%0, %1}, %2;" : "=r"(a), "=r"(b) : "l"(v));
    lo = __uint_as_float(a); hi = __uint_as_float(b);
}

__global__ void __launch_bounds__(256, 1) k_gemmS2(const float* __restrict__ X,
                                                   const float* __restrict__ W) {
    __shared__ float As[2][16][132];   // transposed: As[k][m], padded
    __shared__ float Bs[2][16][132];   // Bs[k][n], padded
    const int tid = threadIdx.x;
    const int tx = tid & 15, ty = tid >> 4;
    const int ncol  = blockIdx.x * 128;
    const int kbase = blockIdx.y * 256;

    const int arow = tid & 127;           // 0..127
    const int acg  = (tid >> 7) << 1;     // 0 or 2 (float4 column-group)
    const int brow = tid >> 4;            // 0..15
    const int bc4  = (tid & 15) << 2;     // 0..60

    const float* Ap = X + (size_t)arow * 4096 + kbase + acg * 4;
    const float* Bp = W + (size_t)(kbase + brow) * 1024 + ncol + bc4;

    float4 av0 = *reinterpret_cast<const float4*>(Ap);
    float4 av1 = *reinterpret_cast<const float4*>(Ap + 4);
    float4 bv0 = *reinterpret_cast<const float4*>(Bp);
    float4 bv1 = *reinterpret_cast<const float4*>(Bp + 64);

    unsigned long long acc[4][8];
    #pragma unroll
    for (int p = 0; p < 4; p++)
        #pragma unroll
        for (int j = 0; j < 8; j++) acc[p][j] = 0ull;

    // stage chunk 0
    As[0][acg * 4 + 0][arow] = av0.x;  As[0][acg * 4 + 1][arow] = av0.y;
    As[0][acg * 4 + 2][arow] = av0.z;  As[0][acg * 4 + 3][arow] = av0.w;
    As[0][acg * 4 + 4][arow] = av1.x;  As[0][acg * 4 + 5][arow] = av1.y;
    As[0][acg * 4 + 6][arow] = av1.z;  As[0][acg * 4 + 7][arow] = av1.w;
    *reinterpret_cast<float4*>(&Bs[0][brow][bc4])      = bv0;
    *reinterpret_cast<float4*>(&Bs[0][brow][64 + bc4]) = bv1;
    __syncthreads();

    int cur = 0;
    #pragma unroll 1
    for (int kc = 0; kc < 16; kc++) {
        if (kc + 1 < 16) {
            av0 = *reinterpret_cast<const float4*>(Ap + (kc + 1) * 16);
            av1 = *reinterpret_cast<const float4*>(Ap + (kc + 1) * 16 + 4);
            bv0 = *reinterpret_cast<const float4*>(Bp + (size_t)(kc + 1) * 16 * 1024);
            bv1 = *reinterpret_cast<const float4*>(Bp + (size_t)(kc + 1) * 16 * 1024 + 64);
        }
        #pragma unroll
        for (int k = 0; k < 16; k++) {
            // A pairs: rows ty*8 + {0,1},{2,3},{4,5},{6,7}  (free reinterpret)
            const unsigned long long* ap =
                reinterpret_cast<const unsigned long long*>(&As[cur][k][ty << 3]);
            unsigned long long a0 = ap[0], a1 = ap[1], a2 = ap[2], a3 = ap[3];
            // B values duplicated into both lanes
            float4 c0 = *reinterpret_cast<const float4*>(&Bs[cur][k][tx << 3]);
            float4 c1 = *reinterpret_cast<const float4*>(&Bs[cur][k][(tx << 3) + 4]);
            unsigned long long bd[8];
            bd[0] = pack_dup(c0.x); bd[1] = pack_dup(c0.y);
            bd[2] = pack_dup(c0.z); bd[3] = pack_dup(c0.w);
            bd[4] = pack_dup(c1.x); bd[5] = pack_dup(c1.y);
            bd[6] = pack_dup(c1.z); bd[7] = pack_dup(c1.w);
            #pragma unroll
            for (int j = 0; j < 8; j++) {
                ffma2(acc[0][j], a0, bd[j]);
                ffma2(acc[1][j], a1, bd[j]);
                ffma2(acc[2][j], a2, bd[j]);
                ffma2(acc[3][j], a3, bd[j]);
            }
        }
        if (kc + 1 < 16) {
            int nxt = cur ^ 1;
            As[nxt][acg * 4 + 0][arow] = av0.x;  As[nxt][acg * 4 + 1][arow] = av0.y;
            As[nxt][acg * 4 + 2][arow] = av0.z;  As[nxt][acg * 4 + 3][arow] = av0.w;
            As[nxt][acg * 4 + 4][arow] = av1.x;  As[nxt][acg * 4 + 5][arow] = av1.y;
            As[nxt][acg * 4 + 6][arow] = av1.z;  As[nxt][acg * 4 + 7][arow] = av1.w;
            *reinterpret_cast<float4*>(&Bs[nxt][brow][bc4])      = bv0;
            *reinterpret_cast<float4*>(&Bs[nxt][brow][64 + bc4]) = bv1;
            __syncthreads();
            cur = nxt;
        }
    }

    // epilogue: unpack pairs -> rows ty*8+2p (lo), +1 (hi)
    float* dst = g_Spart + (size_t)blockIdx.y * 128 * HD;
    #pragma unroll
    for (int p = 0; p < 4; p++) {
        float lo[8], hi[8];
        #pragma unroll
        for (int j = 0; j < 8; j++) unpack2(acc[p][j], lo[j], hi[j]);
        int r = (ty << 3) + (p << 1);
        float4 o;
        o.x = lo[0]; o.y = lo[1]; o.z = lo[2]; o.w = lo[3];
        *reinterpret_cast<float4*>(dst + (size_t)r * HD + ncol + (tx << 3)) = o;
        o.x = lo[4]; o.y = lo[5]; o.z = lo[6]; o.w = lo[7];
        *reinterpret_cast<float4*>(dst + (size_t)r * HD + ncol + (tx << 3) + 4) = o;
        o.x = hi[0]; o.y = hi[1]; o.z = hi[2]; o.w = hi[3];
        *reinterpret_cast<float4*>(dst + (size_t)(r + 1) * HD + ncol + (tx << 3)) = o;
        o.x = hi[4]; o.y = hi[5]; o.z = hi[6]; o.w = hi[7];
        *reinterpret_cast<float4*>(dst + (size_t)(r + 1) * HD + ncol + (tx << 3) + 4) = o;
    }
}

// ---------------- 64x128 SGEMM body (for gemmHP) -----------------------------
__device__ __forceinline__ void sgemm_64x128(
    const float* __restrict__ A, int lda,
    const float* __restrict__ B, int ldb,
    float* __restrict__ C, int ldc,
    int kBase, int kLen)
{
    __shared__ float As[2][16][68];
    __shared__ float Bs[2][16][128];
    const int tid = threadIdx.x;
    const int tx = tid & 15, ty = tid >> 4;
    const int brow = blockIdx.y * 64;
    const int bcol = blockIdx.x * 128;
    const int a_row = tid >> 2;
    const int a_col = (tid & 3) << 2;
    const int b_row = tid >> 4;
    const int b_col = (tid & 15) << 3;

    const float* Aptr = A + (size_t)(brow + a_row) * lda + kBase + a_col;
    const float* Bptr = B + (size_t)(kBase + b_row) * ldb + bcol + b_col;

    float4 av  = *reinterpret_cast<const float4*>(Aptr);
    float4 bv0 = *reinterpret_cast<const float4*>(Bptr);
    float4 bv1 = *reinterpret_cast<const float4*>(Bptr + 4);

    const int T = kLen >> 4;
    float acc[4][8] = {};

    As[0][a_col + 0][a_row] = av.x;
    As[0][a_col + 1][a_row] = av.y;
    As[0][a_col + 2][a_row] = av.z;
    As[0][a_col + 3][a_row] = av.w;
    *reinterpret_cast<float4*>(&Bs[0][b_row][b_col])     = bv0;
    *reinterpret_cast<float4*>(&Bs[0][b_row][b_col + 4]) = bv1;
    __syncthreads();

    int cur = 0;
    for (int t = 0; t < T; t++) {
        if (t + 1 < T) {
            av  = *reinterpret_cast<const float4*>(Aptr + (t + 1) * 16);
            bv0 = *reinterpret_cast<const float4*>(Bptr + (size_t)(t + 1) * 16 * ldb);
            bv1 = *reinterpret_cast<const float4*>(Bptr + (size_t)(t + 1) * 16 * ldb + 4);
        }
        #pragma unroll
        for (int k = 0; k < 16; k++) {
            float4 a4  = *reinterpret_cast<const float4*>(&As[cur][k][ty << 2]);
            float4 b4a = *reinterpret_cast<const float4*>(&Bs[cur][k][tx << 2]);
            float4 b4b = *reinterpret_cast<const float4*>(&Bs[cur][k][64 + (tx << 2)]);
            float ar[4] = {a4.x, a4.y, a4.z, a4.w};
            float br[8] = {b4a.x, b4a.y, b4a.z, b4a.w, b4b.x, b4b.y, b4b.z, b4b.w};
            #pragma unroll
            for (int i = 0; i < 4; i++)
                #pragma unroll
                for (int j = 0; j < 8; j++)
                    acc[i][j] += ar[i] * br[j];
        }
        if (t + 1 < T) {
            int nxt = cur ^ 1;
            As[nxt][a_col + 0][a_row] = av.x;
            As[nxt][a_col + 1][a_row] = av.y;
            As[nxt][a_col + 2][a_row] = av.z;
            As[nxt][a_col + 3][a_row] = av.w;
            *reinterpret_cast<float4*>(&Bs[nxt][b_row][b_col])     = bv0;
            *reinterpret_cast<float4*>(&Bs[nxt][b_row][b_col + 4]) = bv1;
            __syncthreads();
            cur = nxt;
        }
    }
    #pragma unroll
    for (int i = 0; i < 4; i++) {
        int r = brow + (ty << 2) + i;
        float4 o0, o1;
        o0.x = acc[i][0]; o0.y = acc[i][1]; o0.z = acc[i][2]; o0.w = acc[i][3];
        o1.x = acc[i][4]; o1.y = acc[i][5]; o1.z = acc[i][6]; o1.w = acc[i][7];
        *reinterpret_cast<float4*>(&C[(size_t)r * ldc + bcol + (tx << 2)])      = o0;
        *reinterpret_cast<float4*>(&C[(size_t)r * ldc + bcol + 64 + (tx << 2)]) = o1;
    }
}

// hp = attC(512x144) @ Hmat(144x1024)
__global__ void __launch_bounds__(256) k_gemmHP() {
    sgemm_64x128(g_attC, KR, g_Hmat, HD, g_hp, HD, 0, KR);
}

// ---------------- fused: reduce split-K + bias2 -> Hmat row, dot with a -----
__global__ void __launch_bounds__(256) k_redrow(const float* __restrict__ avec) {
    __shared__ float red[8];
    int row = blockIdx.x;              // 0..131
    int t = threadIdx.x;               // 256: one float4 per thread covers the row
    float4 v = make_float4(0.f, 0.f, 0.f, 0.f);
    if (row < 128) {
        #pragma unroll
        for (int z = 0; z < ZS; z++) {
            float4 u = *reinterpret_cast<const float4*>(
                &g_Spart[(size_t)z * 128 * HD + (size_t)row * HD + (t << 2)]);
            v.x += u.x; v.y += u.y; v.z += u.z; v.w += u.w;
        }
    } else {
        int b = row - 128;
        #pragma unroll 8
        for (int r = 0; r < 32; r++) {
            float4 u = *reinterpret_cast<const float4*>(
                &g_b2part[(size_t)(r * 4 + b) * HD + (t << 2)]);
            v.x += u.x; v.y += u.y; v.z += u.z; v.w += u.w;
        }
    }
    *reinterpret_cast<float4*>(&g_Hmat[(size_t)row * HD + (t << 2)]) = v;
    float4 a1 = *reinterpret_cast<const float4*>(&avec[t << 2]);
    float4 a2 = *reinterpret_cast<const float4*>(&avec[HD + (t << 2)]);
    float p1 = v.x * a1.x + v.y * a1.y + v.z * a1.z + v.w * a1.w;
    float p2 = v.x * a2.x + v.y * a2.y + v.z * a2.z + v.w * a2.w;
    int w = t >> 5, l = t & 31;
    for (int o = 16; o > 0; o >>= 1) p1 += __shfl_xor_sync(0xffffffffu, p1, o);
    if (l == 0) red[w] = p1;
    __syncthreads();
    if (t == 0) { float s = 0; for (int i = 0; i < 8; i++) s += red[i]; g_SS1[row] = s; }
    __syncthreads();
    for (int o = 16; o > 0; o >>= 1) p2 += __shfl_xor_sync(0xffffffffu, p2, o);
    if (l == 0) red[w] = p2;
    __syncthreads();
    if (t == 0) { float s = 0; for (int i = 0; i < 8; i++) s += red[i]; g_SS2[row] = s; }
}

// ---------------- softmax row + attC fold + direct new_adj write ------------
__global__ void __launch_bounds__(512) k_softmax(const float* __restrict__ adj_vals,
                                                 float* __restrict__ outp) {
    __shared__ float sw[16];
    __shared__ float sa[16];
    __shared__ float sh[NN];
    __shared__ float s_m, s_Z;
    int n = blockIdx.x, c = threadIdx.x;
    int w = c >> 5, l = c & 31;
    int le = g_last[n * NN + c];
    float s1n = g_SS1[n & 127] + g_SS1[128 + (n >> 7)];
    float ev = 0.f, adv = 0.f;
    if (le >= 0) {
        float x = s1n + g_SS2[c & 127] + g_SS2[128 + (c >> 7)];
        ev = (x > 0.f) ? x : 0.2f * x;
        adv = 2.f * adj_vals[le];
    }
    float r = ev;
    for (int o = 16; o > 0; o >>= 1) r = fmaxf(r, __shfl_xor_sync(0xffffffffu, r, o));
    if (l == 0) sa[w] = r;
    __syncthreads();
    if (w == 0) {
        float m = sa[l & 15];
        for (int o = 8; o > 0; o >>= 1) m = fmaxf(m, __shfl_xor_sync(0xffffffffu, m, o));
        if (l == 0) s_m = m;
    }
    __syncthreads();
    float p = expf(ev - s_m);
    r = p;
    for (int o = 16; o > 0; o >>= 1) r += __shfl_xor_sync(0xffffffffu, r, o);
    if (l == 0) sw[w] = r;
    __syncthreads();
    if (w == 0) {
        float z = (l < 16) ? sw[l] : 0.f;
        for (int o = 16; o > 0; o >>= 1) z += __shfl_xor_sync(0xffffffffu, z, o);
        if (l == 0) s_Z = z;
    }
    __syncthreads();
    float invZ = 1.f / s_Z;
    float att = p * invZ;
    float invA = 1.f / __uint_as_float(g_amax);
    outp[n * NN + c] = att * adv * invA;
    sh[c] = att;
    __syncthreads();
    if (c < 128) {
        g_attC[(size_t)n * KR + c] = sh[c] + sh[c + 128] + sh[c + 256] + sh[c + 384];
    } else if (c < 132) {
        int b = c - 128;
        g_attC[(size_t)n * KR + c] = (sw[4 * b] + sw[4 * b + 1] + sw[4 * b + 2] + sw[4 * b + 3]) * invZ;
    } else if (c < KR) {
        g_attC[(size_t)n * KR + c] = 0.f;
    }
}

// ---------------- out partials: lin_w[i,:] . hp_flat  (HBM-bound, 1.08 GB) --
__global__ void __launch_bounds__(256) k_matvec(const float* __restrict__ lin_w) {
    __shared__ float red[8];
    int i   = blockIdx.y;
    int seg = blockIdx.x;
    const int SEG = (NN * HD) / 16;
    size_t base = (size_t)i * (NN * HD) + (size_t)seg * SEG;
    const float4* wp4 = reinterpret_cast<const float4*>(lin_w + base);
    const float4* vp4 = reinterpret_cast<const float4*>(g_hp + seg * SEG);
    int t = threadIdx.x;
    float s = 0.f;
    #pragma unroll 8
    for (int idx = t; idx < SEG / 4; idx += 256) {
        float4 w = __ldcs(wp4 + idx);
        float4 v = vp4[idx];
        s += w.x * v.x + w.y * v.y + w.z * v.z + w.w * v.w;
    }
    for (int o = 16; o > 0; o >>= 1) s += __shfl_down_sync(0xffffffffu, s, o);
    if ((t & 31) == 0) red[t >> 5] = s;
    __syncthreads();
    if (t == 0) {
        float tot = 0.f;
        for (int w = 0; w < 8; w++) tot += red[w];
        g_outpart[i * 16 + seg] = tot;
    }
}

// ---------------- final: sum partials, min-max normalize 513 outputs --------
__global__ void k_final(const float* __restrict__ lin_b, float* __restrict__ outp) {
    __shared__ float red[16];
    __shared__ float s_mn, s_mx;
    int t = threadIdx.x;
    float v0 = lin_b[t];
    #pragma unroll
    for (int s = 0; s < 16; s++) v0 += g_outpart[t * 16 + s];
    bool has2 = (t == 0);
    float v1 = 0.f;
    if (has2) {
        v1 = lin_b[NN];
        for (int s = 0; s < 16; s++) v1 += g_outpart[NN * 16 + s];
    }
    float mn = v0, mx = v0;
    if (has2) { mn = fminf(mn, v1); mx = fmaxf(mx, v1); }
    float r = mn;
    for (int o = 16; o > 0; o >>= 1) r = fminf(r, __shfl_down_sync(0xffffffffu, r, o));
    if ((t & 31) == 0) red[t >> 5] = r;
    __syncthreads();
    if (t < 32) {
        r = (t < 16) ? red[t] : red[0];
        for (int o = 8; o > 0; o >>= 1) r = fminf(r, __shfl_down_sync(0xffffffffu, r, o));
        if (t == 0) s_mn = r;
    }
    __syncthreads();
    r = mx;
    for (int o = 16; o > 0; o >>= 1) r = fmaxf(r, __shfl_down_sync(0xffffffffu, r, o));
    if ((t & 31) == 0) red[t >> 5] = r;
    __syncthreads();
    if (t < 32) {
        r = (t < 16) ? red[t] : red[0];
        for (int o = 8; o > 0; o >>= 1) r = fmaxf(r, __shfl_down_sync(0xffffffffu, r, o));
        if (t == 0) s_mx = r;
    }
    __syncthreads();
    float mnv = s_mn;
    float den = s_mx - s_mn;
    if (den == 0.f) {
        outp[t] = 0.5f;
        if (has2) outp[NN] = 0.5f;
    } else {
        outp[t] = (v0 - mnv) / den;
        if (has2) outp[NN] = (v1 - mnv) / den;
    }
}

// ---------------- launcher ---------------------------------------------------
extern "C" void kernel_launch(void* const* d_in, const int* in_sizes, int n_in,
                              void* d_out, int out_size) {
    (void)in_sizes; (void)n_in; (void)out_size;
    const float* img   = (const float*)d_in[0];
    const int*   erow  = (const int*)  d_in[1];
    const int*   ecol  = (const int*)  d_in[2];
    const float* adjv  = (const float*)d_in[3];
    const float* X     = (const float*)d_in[4];
    const float* W     = (const float*)d_in[5];
    const float* avec  = (const float*)d_in[6];
    const float* linw  = (const float*)d_in[7];
    const float* linb  = (const float*)d_in[8];
    float* out = (float*)d_out;

    void* p_last = nullptr;  cudaGetSymbolAddress(&p_last, g_last);
    void* p_amax = nullptr;  cudaGetSymbolAddress(&p_amax, g_amax);
    cudaMemsetAsync(p_last, 0xFF, (size_t)NN * NN * sizeof(int), 0);
    cudaMemsetAsync(p_amax, 0x00, sizeof(unsigned), 0);

    k_scatter<<<64, 256>>>(erow, ecol);
    k_amax<<<512, 512>>>(adjv);
    k_bias2<<<dim3(8, 32), 128>>>(W, img);
    k_gemmS2<<<dim3(8, ZS), 256>>>(X, W);
    k_redrow<<<132, 256>>>(avec);
    k_softmax<<<NN, NN>>>(adjv, out);
    k_gemmHP<<<dim3(8, 8, 1), 256>>>();
    k_matvec<<<dim3(16, NN + 1), 256>>>(linw);
    k_final<<<1, NN>>>(linb, out + NN * NN);
}

// round 7
// speedup vs baseline: 1.0264x; 1.0264x over previous
#include <cuda_runtime.h>
#include <cstdint>
#include <cstddef>

// Problem constants
#define NN 512          // nodes
#define HD 1024         // hidden dim
#define NE 16384        // edges
#define KR 144          // padded Hmat rows (128 S + 4 bias2 + 12 zero pad)
#define ZS 32           // split-K factor for gemmS

// ---------------- scratch (device globals; no allocation allowed) ----------
__device__ __align__(16) float g_Spart[ZS * 128 * HD];   // split-K partials for S (16.8 MB)
__device__ __align__(16) float g_b2part[32 * 4 * HD];    // bias2 partials
__device__ __align__(16) float g_Hmat[KR * HD];          // 0..127 S, 128..131 bias2, 132..143 stay 0
__device__ __align__(16) float g_attC[NN * KR];          // folded attention (512 x 144)
__device__ __align__(16) float g_hp[NN * HD];            // h_prime (512 x 1024)
__device__ int      g_last[NN * NN];
__device__ float    g_SS1[132];
__device__ float    g_SS2[132];
__device__ float    g_outpart[(NN + 1) * 16];            // matvec partials
__device__ unsigned g_amax;

// ---------------- scatter: last-edge-wins per dense cell --------------------
__global__ void k_scatter(const int* __restrict__ er, const int* __restrict__ ec) {
    int k = blockIdx.x * blockDim.x + threadIdx.x;
    if (k < NE) atomicMax(&g_last[er[k] * NN + ec[k]], k);
}

// ---------------- amax of dense adj2 (cells with last-edge set; all >= 0) ---
__global__ void k_amax(const float* __restrict__ adj_vals) {
    __shared__ float sa[16];
    int idx = blockIdx.x * blockDim.x + threadIdx.x;
    int t = threadIdx.x, w = t >> 5, l = t & 31;
    float m = 0.f;
    int le = g_last[idx];
    if (le >= 0) m = 2.f * adj_vals[le];
    for (int o = 16; o > 0; o >>= 1) m = fmaxf(m, __shfl_xor_sync(0xffffffffu, m, o));
    if (l == 0) sa[w] = m;
    __syncthreads();
    if (t == 0) {
        float mm = 0.f;
        for (int i = 0; i < 16; i++) mm = fmaxf(mm, sa[i]);
        atomicMax(&g_amax, __float_as_uint(mm));
    }
}

// ---------------- bias2 partials: chunk rc of rho, 4 batch outputs ----------
__global__ void k_bias2(const float* __restrict__ W, const float* __restrict__ img) {
    int j  = blockIdx.x * 128 + threadIdx.x;
    int rc = blockIdx.y;
    int r0 = rc * 128;
    float a0 = 0.f, a1 = 0.f, a2 = 0.f, a3 = 0.f;
    #pragma unroll 4
    for (int rr = 0; rr < 128; rr++) {
        int rho = r0 + rr;
        float w = W[(size_t)rho * HD + j];
        int d = rho & 1023;
        a0 += img[d]        * w;
        a1 += img[1024 + d] * w;
        a2 += img[2048 + d] * w;
        a3 += img[3072 + d] * w;
    }
    g_b2part[(rc * 4 + 0) * HD + j] = a0;
    g_b2part[(rc * 4 + 1) * HD + j] = a1;
    g_b2part[(rc * 4 + 2) * HD + j] = a2;
    g_b2part[(rc * 4 + 3) * HD + j] = a3;
}

// ================= gemmS: 128x128 tile, 8x8 micro, 2 CTAs/SM ================
// Grid (8, 32): blockIdx.x = N-tile (128 cols), blockIdx.y = K-split (128 K).
// S partial: g_Spart[z] = Xr(128x4096)[:, z*128:(z+1)*128] @ W[z*128:(z+1)*128, :]
__global__ void __launch_bounds__(256, 2) k_gemmS3(const float* __restrict__ X,
                                                   const float* __restrict__ W) {
    __shared__ float As[2][16][132];   // transposed: As[k][m], 528B rows (16B aligned)
    __shared__ float Bs[2][16][132];   // Bs[k][n]
    const int tid = threadIdx.x;
    const int tx = tid & 15, ty = tid >> 4;
    const int ncol  = blockIdx.x * 128;
    const int kbase = blockIdx.y * 128;

    // A staging: 512 float4 slots; thread covers slots {tid, tid+256}
    const int ar0 = tid >> 2;          // rows 0..63 (slot1 adds +64)
    const int acg = (tid & 3) << 2;    // k-offset 0,4,8,12
    // B staging: 512 float4 slots; thread covers slots {tid, tid+256}
    const int bk0 = tid >> 5;          // krow 0..7 (slot1 adds +8)
    const int bc4 = (tid & 31) << 2;   // col 0..124

    const float* Ap = X + (size_t)ar0 * 4096 + kbase + acg;
    const float* Bp = W + (size_t)(kbase + bk0) * 1024 + ncol + bc4;

    float4 a0 = *reinterpret_cast<const float4*>(Ap);
    float4 a1 = *reinterpret_cast<const float4*>(Ap + 64 * 4096);
    float4 b0 = *reinterpret_cast<const float4*>(Bp);
    float4 b1 = *reinterpret_cast<const float4*>(Bp + 8 * 1024);

    float acc[8][8];
    #pragma unroll
    for (int i = 0; i < 8; i++)
        #pragma unroll
        for (int j = 0; j < 8; j++) acc[i][j] = 0.f;

    // stage chunk 0
    As[0][acg + 0][ar0] = a0.x;  As[0][acg + 1][ar0] = a0.y;
    As[0][acg + 2][ar0] = a0.z;  As[0][acg + 3][ar0] = a0.w;
    As[0][acg + 0][ar0 + 64] = a1.x;  As[0][acg + 1][ar0 + 64] = a1.y;
    As[0][acg + 2][ar0 + 64] = a1.z;  As[0][acg + 3][ar0 + 64] = a1.w;
    *reinterpret_cast<float4*>(&Bs[0][bk0][bc4])     = b0;
    *reinterpret_cast<float4*>(&Bs[0][bk0 + 8][bc4]) = b1;
    __syncthreads();

    int cur = 0;
    #pragma unroll 1
    for (int t = 0; t < 8; t++) {
        if (t + 1 < 8) {
            a0 = *reinterpret_cast<const float4*>(Ap + (t + 1) * 16);
            a1 = *reinterpret_cast<const float4*>(Ap + (t + 1) * 16 + 64 * 4096);
            b0 = *reinterpret_cast<const float4*>(Bp + (size_t)(t + 1) * 16 * 1024);
            b1 = *reinterpret_cast<const float4*>(Bp + (size_t)(t + 1) * 16 * 1024 + 8 * 1024);
        }
        #pragma unroll
        for (int k = 0; k < 16; k++) {
            float4 ar0v = *reinterpret_cast<const float4*>(&As[cur][k][ty << 3]);
            float4 ar1v = *reinterpret_cast<const float4*>(&As[cur][k][(ty << 3) + 4]);
            float4 bc0v = *reinterpret_cast<const float4*>(&Bs[cur][k][tx << 2]);
            float4 bc1v = *reinterpret_cast<const float4*>(&Bs[cur][k][64 + (tx << 2)]);
            float ar[8] = {ar0v.x, ar0v.y, ar0v.z, ar0v.w, ar1v.x, ar1v.y, ar1v.z, ar1v.w};
            float br[8] = {bc0v.x, bc0v.y, bc0v.z, bc0v.w, bc1v.x, bc1v.y, bc1v.z, bc1v.w};
            #pragma unroll
            for (int i = 0; i < 8; i++)
                #pragma unroll
                for (int j = 0; j < 8; j++)
                    acc[i][j] += ar[i] * br[j];
        }
        if (t + 1 < 8) {
            int nxt = cur ^ 1;
            As[nxt][acg + 0][ar0] = a0.x;  As[nxt][acg + 1][ar0] = a0.y;
            As[nxt][acg + 2][ar0] = a0.z;  As[nxt][acg + 3][ar0] = a0.w;
            As[nxt][acg + 0][ar0 + 64] = a1.x;  As[nxt][acg + 1][ar0 + 64] = a1.y;
            As[nxt][acg + 2][ar0 + 64] = a1.z;  As[nxt][acg + 3][ar0 + 64] = a1.w;
            *reinterpret_cast<float4*>(&Bs[nxt][bk0][bc4])     = b0;
            *reinterpret_cast<float4*>(&Bs[nxt][bk0 + 8][bc4]) = b1;
            __syncthreads();
            cur = nxt;
        }
    }

    float* dst = g_Spart + (size_t)blockIdx.y * 128 * HD;
    #pragma unroll
    for (int i = 0; i < 8; i++) {
        int r = (ty << 3) + i;
        float4 o0, o1;
        o0.x = acc[i][0]; o0.y = acc[i][1]; o0.z = acc[i][2]; o0.w = acc[i][3];
        o1.x = acc[i][4]; o1.y = acc[i][5]; o1.z = acc[i][6]; o1.w = acc[i][7];
        *reinterpret_cast<float4*>(dst + (size_t)r * HD + ncol + (tx << 2))      = o0;
        *reinterpret_cast<float4*>(dst + (size_t)r * HD + ncol + 64 + (tx << 2)) = o1;
    }
}

// ---------------- 64x128 SGEMM body (for gemmHP) -----------------------------
__device__ __forceinline__ void sgemm_64x128(
    const float* __restrict__ A, int lda,
    const float* __restrict__ B, int ldb,
    float* __restrict__ C, int ldc,
    int kBase, int kLen)
{
    __shared__ float As[2][16][68];
    __shared__ float Bs[2][16][128];
    const int tid = threadIdx.x;
    const int tx = tid & 15, ty = tid >> 4;
    const int brow = blockIdx.y * 64;
    const int bcol = blockIdx.x * 128;
    const int a_row = tid >> 2;
    const int a_col = (tid & 3) << 2;
    const int b_row = tid >> 4;
    const int b_col = (tid & 15) << 3;

    const float* Aptr = A + (size_t)(brow + a_row) * lda + kBase + a_col;
    const float* Bptr = B + (size_t)(kBase + b_row) * ldb + bcol + b_col;

    float4 av  = *reinterpret_cast<const float4*>(Aptr);
    float4 bv0 = *reinterpret_cast<const float4*>(Bptr);
    float4 bv1 = *reinterpret_cast<const float4*>(Bptr + 4);

    const int T = kLen >> 4;
    float acc[4][8] = {};

    As[0][a_col + 0][a_row] = av.x;
    As[0][a_col + 1][a_row] = av.y;
    As[0][a_col + 2][a_row] = av.z;
    As[0][a_col + 3][a_row] = av.w;
    *reinterpret_cast<float4*>(&Bs[0][b_row][b_col])     = bv0;
    *reinterpret_cast<float4*>(&Bs[0][b_row][b_col + 4]) = bv1;
    __syncthreads();

    int cur = 0;
    for (int t = 0; t < T; t++) {
        if (t + 1 < T) {
            av  = *reinterpret_cast<const float4*>(Aptr + (t + 1) * 16);
            bv0 = *reinterpret_cast<const float4*>(Bptr + (size_t)(t + 1) * 16 * ldb);
            bv1 = *reinterpret_cast<const float4*>(Bptr + (size_t)(t + 1) * 16 * ldb + 4);
        }
        #pragma unroll
        for (int k = 0; k < 16; k++) {
            float4 a4  = *reinterpret_cast<const float4*>(&As[cur][k][ty << 2]);
            float4 b4a = *reinterpret_cast<const float4*>(&Bs[cur][k][tx << 2]);
            float4 b4b = *reinterpret_cast<const float4*>(&Bs[cur][k][64 + (tx << 2)]);
            float ar[4] = {a4.x, a4.y, a4.z, a4.w};
            float br[8] = {b4a.x, b4a.y, b4a.z, b4a.w, b4b.x, b4b.y, b4b.z, b4b.w};
            #pragma unroll
            for (int i = 0; i < 4; i++)
                #pragma unroll
                for (int j = 0; j < 8; j++)
                    acc[i][j] += ar[i] * br[j];
        }
        if (t + 1 < T) {
            int nxt = cur ^ 1;
            As[nxt][a_col + 0][a_row] = av.x;
            As[nxt][a_col + 1][a_row] = av.y;
            As[nxt][a_col + 2][a_row] = av.z;
            As[nxt][a_col + 3][a_row] = av.w;
            *reinterpret_cast<float4*>(&Bs[nxt][b_row][b_col])     = bv0;
            *reinterpret_cast<float4*>(&Bs[nxt][b_row][b_col + 4]) = bv1;
            __syncthreads();
            cur = nxt;
        }
    }
    #pragma unroll
    for (int i = 0; i < 4; i++) {
        int r = brow + (ty << 2) + i;
        float4 o0, o1;
        o0.x = acc[i][0]; o0.y = acc[i][1]; o0.z = acc[i][2]; o0.w = acc[i][3];
        o1.x = acc[i][4]; o1.y = acc[i][5]; o1.z = acc[i][6]; o1.w = acc[i][7];
        *reinterpret_cast<float4*>(&C[(size_t)r * ldc + bcol + (tx << 2)])      = o0;
        *reinterpret_cast<float4*>(&C[(size_t)r * ldc + bcol + 64 + (tx << 2)]) = o1;
    }
}

// hp = attC(512x144) @ Hmat(144x1024)
__global__ void __launch_bounds__(256) k_gemmHP() {
    sgemm_64x128(g_attC, KR, g_Hmat, HD, g_hp, HD, 0, KR);
}

// ---------------- fused: reduce split-K + bias2 -> Hmat row, dot with a -----
__global__ void __launch_bounds__(256) k_redrow(const float* __restrict__ avec) {
    __shared__ float red[8];
    int row = blockIdx.x;              // 0..131
    int t = threadIdx.x;               // 256: one float4 per thread covers the row
    float4 v = make_float4(0.f, 0.f, 0.f, 0.f);
    if (row < 128) {
        #pragma unroll
        for (int z = 0; z < ZS; z++) {
            float4 u = *reinterpret_cast<const float4*>(
                &g_Spart[(size_t)z * 128 * HD + (size_t)row * HD + (t << 2)]);
            v.x += u.x; v.y += u.y; v.z += u.z; v.w += u.w;
        }
    } else {
        int b = row - 128;
        #pragma unroll 8
        for (int r = 0; r < 32; r++) {
            float4 u = *reinterpret_cast<const float4*>(
                &g_b2part[(size_t)(r * 4 + b) * HD + (t << 2)]);
            v.x += u.x; v.y += u.y; v.z += u.z; v.w += u.w;
        }
    }
    *reinterpret_cast<float4*>(&g_Hmat[(size_t)row * HD + (t << 2)]) = v;
    float4 a1 = *reinterpret_cast<const float4*>(&avec[t << 2]);
    float4 a2 = *reinterpret_cast<const float4*>(&avec[HD + (t << 2)]);
    float p1 = v.x * a1.x + v.y * a1.y + v.z * a1.z + v.w * a1.w;
    float p2 = v.x * a2.x + v.y * a2.y + v.z * a2.z + v.w * a2.w;
    int w = t >> 5, l = t & 31;
    for (int o = 16; o > 0; o >>= 1) p1 += __shfl_xor_sync(0xffffffffu, p1, o);
    if (l == 0) red[w] = p1;
    __syncthreads();
    if (t == 0) { float s = 0; for (int i = 0; i < 8; i++) s += red[i]; g_SS1[row] = s; }
    __syncthreads();
    for (int o = 16; o > 0; o >>= 1) p2 += __shfl_xor_sync(0xffffffffu, p2, o);
    if (l == 0) red[w] = p2;
    __syncthreads();
    if (t == 0) { float s = 0; for (int i = 0; i < 8; i++) s += red[i]; g_SS2[row] = s; }
}

// ---------------- softmax row + attC fold + direct new_adj write ------------
__global__ void __launch_bounds__(512) k_softmax(const float* __restrict__ adj_vals,
                                                 float* __restrict__ outp) {
    __shared__ float sw[16];
    __shared__ float sa[16];
    __shared__ float sh[NN];
    __shared__ float s_m, s_Z;
    int n = blockIdx.x, c = threadIdx.x;
    int w = c >> 5, l = c & 31;
    int le = g_last[n * NN + c];
    float s1n = g_SS1[n & 127] + g_SS1[128 + (n >> 7)];
    float ev = 0.f, adv = 0.f;
    if (le >= 0) {
        float x = s1n + g_SS2[c & 127] + g_SS2[128 + (c >> 7)];
        ev = (x > 0.f) ? x : 0.2f * x;
        adv = 2.f * adj_vals[le];
    }
    float r = ev;
    for (int o = 16; o > 0; o >>= 1) r = fmaxf(r, __shfl_xor_sync(0xffffffffu, r, o));
    if (l == 0) sa[w] = r;
    __syncthreads();
    if (w == 0) {
        float m = sa[l & 15];
        for (int o = 8; o > 0; o >>= 1) m = fmaxf(m, __shfl_xor_sync(0xffffffffu, m, o));
        if (l == 0) s_m = m;
    }
    __syncthreads();
    float p = expf(ev - s_m);
    r = p;
    for (int o = 16; o > 0; o >>= 1) r += __shfl_xor_sync(0xffffffffu, r, o);
    if (l == 0) sw[w] = r;
    __syncthreads();
    if (w == 0) {
        float z = (l < 16) ? sw[l] : 0.f;
        for (int o = 16; o > 0; o >>= 1) z += __shfl_xor_sync(0xffffffffu, z, o);
        if (l == 0) s_Z = z;
    }
    __syncthreads();
    float invZ = 1.f / s_Z;
    float att = p * invZ;
    float invA = 1.f / __uint_as_float(g_amax);
    outp[n * NN + c] = att * adv * invA;
    sh[c] = att;
    __syncthreads();
    if (c < 128) {
        g_attC[(size_t)n * KR + c] = sh[c] + sh[c + 128] + sh[c + 256] + sh[c + 384];
    } else if (c < 132) {
        int b = c - 128;
        g_attC[(size_t)n * KR + c] = (sw[4 * b] + sw[4 * b + 1] + sw[4 * b + 2] + sw[4 * b + 3]) * invZ;
    } else if (c < KR) {
        g_attC[(size_t)n * KR + c] = 0.f;
    }
}

// ---------------- out partials: lin_w[i,:] . hp_flat  (HBM-bound, 1.08 GB) --
__global__ void __launch_bounds__(256) k_matvec(const float* __restrict__ lin_w) {
    __shared__ float red[8];
    int i   = blockIdx.y;
    int seg = blockIdx.x;
    const int SEG = (NN * HD) / 16;
    size_t base = (size_t)i * (NN * HD) + (size_t)seg * SEG;
    const float4* wp4 = reinterpret_cast<const float4*>(lin_w + base);
    const float4* vp4 = reinterpret_cast<const float4*>(g_hp + seg * SEG);
    int t = threadIdx.x;
    float s = 0.f;
    #pragma unroll 8
    for (int idx = t; idx < SEG / 4; idx += 256) {
        float4 w = __ldcs(wp4 + idx);
        float4 v = vp4[idx];
        s += w.x * v.x + w.y * v.y + w.z * v.z + w.w * v.w;
    }
    for (int o = 16; o > 0; o >>= 1) s += __shfl_down_sync(0xffffffffu, s, o);
    if ((t & 31) == 0) red[t >> 5] = s;
    __syncthreads();
    if (t == 0) {
        float tot = 0.f;
        for (int w = 0; w < 8; w++) tot += red[w];
        g_outpart[i * 16 + seg] = tot;
    }
}

// ---------------- final: sum partials, min-max normalize 513 outputs --------
__global__ void k_final(const float* __restrict__ lin_b, float* __restrict__ outp) {
    __shared__ float red[16];
    __shared__ float s_mn, s_mx;
    int t = threadIdx.x;
    float v0 = lin_b[t];
    #pragma unroll
    for (int s = 0; s < 16; s++) v0 += g_outpart[t * 16 + s];
    bool has2 = (t == 0);
    float v1 = 0.f;
    if (has2) {
        v1 = lin_b[NN];
        for (int s = 0; s < 16; s++) v1 += g_outpart[NN * 16 + s];
    }
    float mn = v0, mx = v0;
    if (has2) { mn = fminf(mn, v1); mx = fmaxf(mx, v1); }
    float r = mn;
    for (int o = 16; o > 0; o >>= 1) r = fminf(r, __shfl_down_sync(0xffffffffu, r, o));
    if ((t & 31) == 0) red[t >> 5] = r;
    __syncthreads();
    if (t < 32) {
        r = (t < 16) ? red[t] : red[0];
        for (int o = 8; o > 0; o >>= 1) r = fminf(r, __shfl_down_sync(0xffffffffu, r, o));
        if (t == 0) s_mn = r;
    }
    __syncthreads();
    r = mx;
    for (int o = 16; o > 0; o >>= 1) r = fmaxf(r, __shfl_down_sync(0xffffffffu, r, o));
    if ((t & 31) == 0) red[t >> 5] = r;
    __syncthreads();
    if (t < 32) {
        r = (t < 16) ? red[t] : red[0];
        for (int o = 8; o > 0; o >>= 1) r = fmaxf(r, __shfl_down_sync(0xffffffffu, r, o));
        if (t == 0) s_mx = r;
    }
    __syncthreads();
    float mnv = s_mn;
    float den = s_mx - s_mn;
    if (den == 0.f) {
        outp[t] = 0.5f;
        if (has2) outp[NN] = 0.5f;
    } else {
        outp[t] = (v0 - mnv) / den;
        if (has2) outp[NN] = (v1 - mnv) / den;
    }
}

// ---------------- launcher ---------------------------------------------------
extern "C" void kernel_launch(void* const* d_in, const int* in_sizes, int n_in,
                              void* d_out, int out_size) {
    (void)in_sizes; (void)n_in; (void)out_size;
    const float* img   = (const float*)d_in[0];
    const int*   erow  = (const int*)  d_in[1];
    const int*   ecol  = (const int*)  d_in[2];
    const float* adjv  = (const float*)d_in[3];
    const float* X     = (const float*)d_in[4];
    const float* W     = (const float*)d_in[5];
    const float* avec  = (const float*)d_in[6];
    const float* linw  = (const float*)d_in[7];
    const float* linb  = (const float*)d_in[8];
    float* out = (float*)d_out;

    void* p_last = nullptr;  cudaGetSymbolAddress(&p_last, g_last);
    void* p_amax = nullptr;  cudaGetSymbolAddress(&p_amax, g_amax);
    cudaMemsetAsync(p_last, 0xFF, (size_t)NN * NN * sizeof(int), 0);
    cudaMemsetAsync(p_amax, 0x00, sizeof(unsigned), 0);

    k_scatter<<<64, 256>>>(erow, ecol);
    k_amax<<<512, 512>>>(adjv);
    k_bias2<<<dim3(8, 32), 128>>>(W, img);
    k_gemmS3<<<dim3(8, ZS), 256>>>(X, W);
    k_redrow<<<132, 256>>>(avec);
    k_softmax<<<NN, NN>>>(adjv, out);
    k_gemmHP<<<dim3(8, 8, 1), 256>>>();
    k_matvec<<<dim3(16, NN + 1), 256>>>(linw);
    k_final<<<1, NN>>>(linb, out + NN * NN);
}